// round 12
// baseline (speedup 1.0000x reference)
#include <cuda_runtime.h>
#include <cuda_fp16.h>
#include <float.h>
#include <stdint.h>

// ---------------------------------------------------------------------------
// Problem constants
// ---------------------------------------------------------------------------
#define BATCH   16
#define CDIM    256
#define HW      1024
#define NROWS   16384          // BATCH*HW
#define KCODES  8192
#define NELEM   4194304        // BATCH*CDIM*HW

// GEMM config: single-pass fp16 hi*hi (K = 256 halves, 4 chunks of 64).
// B pre-scaled by 2^12; exact fp32 rescore fixes approximation afterwards.
#define MTILE       256
#define NTILE       128
#define NCHUNKS     64         // 8192 / 128 n-chunks per row
#define NKCH        4
#define STAGES      4
#define STAGE_BYTES 49152      // A 32K (256 rows x 128B) + B 16K (128 x 128B)
#define B_OFF       32768
#define SMEM_NEED   (STAGES * STAGE_BYTES)   // 192 KB

#define RESCORE_EPS 2e-4f      // >= 2 * worst-case fp16-approx distance error

// ---------------------------------------------------------------------------
// Device scratch (no cudaMalloc allowed)
// ---------------------------------------------------------------------------
__device__ __align__(16) __half g_Ahi[NROWS * CDIM];
__device__ __align__(16) __half g_Bhi[KCODES * CDIM];
__device__ __align__(16) float  g_zT [NROWS * CDIM];   // exact fp32, (n,c)
__device__ float g_esq[KCODES];
__device__ float g_zsq[NROWS];
__device__ float g_pmin2[NROWS * NCHUNKS * 2];
__device__ int   g_pidx2[NROWS * NCHUNKS * 2];
__device__ int   g_codes[NROWS];
__device__ float g_partial[2048];

// ---------------------------------------------------------------------------
// Helpers
// ---------------------------------------------------------------------------
__device__ __forceinline__ uint32_t smem_u32(const void* p) {
    uint32_t a;
    asm("{ .reg .u64 t; cvta.to.shared.u64 t, %1; cvt.u32.u64 %0, t; }"
        : "=r"(a) : "l"(p));
    return a;
}

// SW128-style swizzle (relative to tile base; 16B-granular)
#define SWZ(o) ((o) ^ (((o) >> 3) & 0x70))

__device__ __forceinline__ void cp_async16(uint32_t dst, const void* src) {
    asm volatile("cp.async.cg.shared.global [%0], [%1], 16;"
                 :: "r"(dst), "l"(src) : "memory");
}
#define CP_COMMIT() asm volatile("cp.async.commit_group;" ::: "memory")

__device__ __forceinline__ void mma_f16(float* c, const uint32_t* a,
                                        const uint32_t* b) {
    asm volatile(
        "mma.sync.aligned.m16n8k16.row.col.f32.f16.f16.f32 "
        "{%0,%1,%2,%3}, {%4,%5,%6,%7}, {%8,%9}, {%0,%1,%2,%3};"
        : "+f"(c[0]), "+f"(c[1]), "+f"(c[2]), "+f"(c[3])
        : "r"(a[0]), "r"(a[1]), "r"(a[2]), "r"(a[3]), "r"(b[0]), "r"(b[1]));
}

// top-2 insert / merge with deterministic (value, index) ordering
__device__ __forceinline__ void top2_ins(float& b1, int& i1, float& b2, int& i2,
                                         float d, int n) {
    if (d < b1 || (d == b1 && n < i1)) { b2 = b1; i2 = i1; b1 = d; i1 = n; }
    else if (d < b2 || (d == b2 && n < i2)) { b2 = d; i2 = n; }
}
__device__ __forceinline__ void top2_merge(float& b1, int& i1, float& b2, int& i2,
                                           float w1, int j1, float w2, int j2) {
    top2_ins(b1, i1, b2, i2, w1, j1);
    top2_ins(b1, i1, b2, i2, w2, j2);
}

// ---------------------------------------------------------------------------
// e_sq[k] = sum_c codebook[k][c]^2   (original fp32 data)
// ---------------------------------------------------------------------------
__global__ void vq_esq_kernel(const float* __restrict__ cbk) {
    int k    = blockIdx.x * 8 + (threadIdx.x >> 5);
    int lane = threadIdx.x & 31;
    const float4* row = (const float4*)(cbk + (size_t)k * CDIM);
    float s = 0.f;
    #pragma unroll
    for (int i = lane; i < CDIM / 4; i += 32) {
        float4 v = row[i];
        s += v.x * v.x + v.y * v.y + v.z * v.z + v.w * v.w;
    }
    #pragma unroll
    for (int off = 16; off > 0; off >>= 1)
        s += __shfl_down_sync(0xffffffffu, s, off);
    if (lane == 0) g_esq[k] = s;
}

// ---------------------------------------------------------------------------
// z_sq[n] from the transposed fp32 copy (coalesced; run AFTER vq_split_z)
// ---------------------------------------------------------------------------
__global__ void vq_zsq_kernel() {
    int n    = blockIdx.x * 8 + (threadIdx.x >> 5);
    int lane = threadIdx.x & 31;
    const float4* row = (const float4*)(g_zT + (size_t)n * CDIM);
    float s = 0.f;
    #pragma unroll
    for (int i = lane; i < CDIM / 4; i += 32) {
        float4 v = row[i];
        s += v.x * v.x + v.y * v.y + v.z * v.z + v.w * v.w;
    }
    #pragma unroll
    for (int off = 16; off > 0; off >>= 1)
        s += __shfl_down_sync(0xffffffffu, s, off);
    if (lane == 0) g_zsq[n] = s;
}

// ---------------------------------------------------------------------------
// Split z -> fp16 hi (for GEMM) + exact fp32 transposed copy (for rescore)
// ---------------------------------------------------------------------------
__global__ void vq_split_z(const float* __restrict__ z) {
    __shared__ float t[32][33];
    int b   = blockIdx.z;
    int c0  = blockIdx.y * 32;
    int hw0 = blockIdx.x * 32;
    int tx  = threadIdx.x & 31;
    int ty  = threadIdx.x >> 5;        // 0..7
    const float* src = z + ((size_t)b * CDIM + c0) * HW + hw0;
    #pragma unroll
    for (int j = 0; j < 4; j++) {
        int c = ty + j * 8;
        t[c][tx] = src[(size_t)c * HW + tx];
    }
    __syncthreads();
    #pragma unroll
    for (int j = 0; j < 4; j++) {
        int hh = ty + j * 8;
        float a  = t[tx][hh];
        size_t o = ((size_t)(b * HW + hw0 + hh)) * CDIM + c0 + tx;
        g_Ahi[o] = __float2half_rn(a);
        g_zT[o]  = a;
    }
}

// ---------------------------------------------------------------------------
// Split codebook -> fp16 hi, pre-scaled by 2^12 (exact power of two)
// ---------------------------------------------------------------------------
__global__ void vq_split_cb(const float* __restrict__ cbk) {
    int i = blockIdx.x * 256 + threadIdx.x;
    g_Bhi[i] = __float2half_rn(cbk[i] * 4096.0f);
}

// ---------------------------------------------------------------------------
// Stage loader: chunk c (0..3) into pipeline slot s.
// A: 256 rows x 128B (64 halves); B: 128 rows x 128B.
// ---------------------------------------------------------------------------
__device__ __forceinline__ void load_stage(uint32_t sbu, int c, int s,
                                           int m0, int n0, int tid) {
    int kb = c * 64;                        // halves
    uint32_t st = sbu + s * STAGE_BYTES;
    #pragma unroll
    for (int j = 0; j < 8; j++) {           // A: 2048 cp16
        int id = j * 256 + tid;
        int r = id >> 3, q = id & 7;
        cp_async16(st + SWZ(r * 128 + q * 16),
                   g_Ahi + (size_t)(m0 + r) * CDIM + kb + q * 8);
    }
    #pragma unroll
    for (int j = 0; j < 4; j++) {           // B: 1024 cp16
        int id = j * 256 + tid;
        int r = id >> 3, q = id & 7;
        cp_async16(st + B_OFF + SWZ(r * 128 + q * 16),
                   g_Bhi + (size_t)(n0 + r) * CDIM + kb + q * 8);
    }
}

// ---------------------------------------------------------------------------
// Main mma.sync fp16 GEMM + fused approx distance / top-2 per chunk.
// Grid: 4096 CTAs = 64 m-tiles (256 rows) x 64 n-chunks (128 codes).
// 8 warps, warp tile 64x64.
// ---------------------------------------------------------------------------
__global__ __launch_bounds__(256, 1) void vq_gemm() {
    extern __shared__ char smem_raw[];
    const uint32_t sbu = smem_u32(smem_raw);
    const int tid  = threadIdx.x;
    const int lane = tid & 31;
    const int wid  = tid >> 5;
    const int wm   = wid & 3;          // 4 m-blocks of 64
    const int wn   = wid >> 2;         // 2 n-blocks of 64
    const int gq   = lane >> 2;        // 0..7
    const int tq   = lane & 3;         // 0..3

    const int nt_blk = blockIdx.x & 63;
    const int mt_blk = blockIdx.x >> 6;
    const int m0 = mt_blk * MTILE;
    const int n0 = nt_blk * NTILE;

    const uint32_t rxor = (uint32_t)gq << 4;
    uint32_t coff[8];
    #pragma unroll
    for (int ks = 0; ks < 4; ks++) {
        uint32_t base = ks * 32 + tq * 4;
        coff[2 * ks]     = base ^ rxor;
        coff[2 * ks + 1] = (base + 16) ^ rxor;
    }
    uint32_t rA[4], rB[8];
    #pragma unroll
    for (int mt = 0; mt < 4; mt++) rA[mt] = (uint32_t)(wm * 64 + mt * 16 + gq) * 128;
    #pragma unroll
    for (int nt = 0; nt < 8; nt++) rB[nt] = (uint32_t)(wn * 64 + nt * 8 + gq) * 128;

    float acc[4][8][4];
    #pragma unroll
    for (int mt = 0; mt < 4; mt++)
        #pragma unroll
        for (int nt = 0; nt < 8; nt++)
            #pragma unroll
            for (int r = 0; r < 4; r++) acc[mt][nt][r] = 0.f;

    #pragma unroll
    for (int s = 0; s < 3; s++) { load_stage(sbu, s, s, m0, n0, tid); CP_COMMIT(); }

    for (int c = 0; c < NKCH; c++) {
        if (c < NKCH - 2)       asm volatile("cp.async.wait_group 2;" ::: "memory");
        else if (c == NKCH - 2) asm volatile("cp.async.wait_group 1;" ::: "memory");
        else                    asm volatile("cp.async.wait_group 0;" ::: "memory");
        __syncthreads();
        if (c + 3 < NKCH) { load_stage(sbu, c + 3, (c + 3) & 3, m0, n0, tid); CP_COMMIT(); }

        const char* stA = smem_raw + (c & 3) * STAGE_BYTES;
        const char* stB = stA + B_OFF;
        #pragma unroll
        for (int ks = 0; ks < 4; ks++) {
            uint32_t a[4][4], b[8][2];
            #pragma unroll
            for (int mt = 0; mt < 4; mt++) {
                a[mt][0] = *(const uint32_t*)(stA + rA[mt] + coff[2 * ks]);
                a[mt][1] = *(const uint32_t*)(stA + rA[mt] + 1024 + coff[2 * ks]);
                a[mt][2] = *(const uint32_t*)(stA + rA[mt] + coff[2 * ks + 1]);
                a[mt][3] = *(const uint32_t*)(stA + rA[mt] + 1024 + coff[2 * ks + 1]);
            }
            #pragma unroll
            for (int nt = 0; nt < 8; nt++) {
                b[nt][0] = *(const uint32_t*)(stB + rB[nt] + coff[2 * ks]);
                b[nt][1] = *(const uint32_t*)(stB + rB[nt] + coff[2 * ks + 1]);
            }
            #pragma unroll
            for (int mt = 0; mt < 4; mt++)
                #pragma unroll
                for (int nt = 0; nt < 8; nt++)
                    mma_f16(acc[mt][nt], a[mt], b[nt]);
        }
    }

    __syncthreads();   // stages done; smem reused for reduction

    // Epilogue: approx distances (unscale folded: -2 * 2^-12), top-2 per row.
    float* sval = (float*)smem_raw;            // [256 rows][2 wn][2]
    int*   sidx = (int*)(smem_raw + 4096);

    #pragma unroll
    for (int mt = 0; mt < 4; mt++) {
        const int rl  = wm * 64 + mt * 16 + gq;
        const float zlo = g_zsq[m0 + rl];
        const float zhi = g_zsq[m0 + rl + 8];
        float b1l = FLT_MAX, b2l = FLT_MAX, b1h = FLT_MAX, b2h = FLT_MAX;
        int   i1l = 0x7fffffff, i2l = 0x7fffffff;
        int   i1h = 0x7fffffff, i2h = 0x7fffffff;
        #pragma unroll
        for (int nt = 0; nt < 8; nt++) {
            const int nA = n0 + wn * 64 + nt * 8 + 2 * tq;
            const float e0 = __ldg(&g_esq[nA]);
            const float e1 = __ldg(&g_esq[nA + 1]);
            float d;
            d = fmaf(-0x1p-11f, acc[mt][nt][0], zlo) + e0; top2_ins(b1l,i1l,b2l,i2l,d,nA);
            d = fmaf(-0x1p-11f, acc[mt][nt][1], zlo) + e1; top2_ins(b1l,i1l,b2l,i2l,d,nA+1);
            d = fmaf(-0x1p-11f, acc[mt][nt][2], zhi) + e0; top2_ins(b1h,i1h,b2h,i2h,d,nA);
            d = fmaf(-0x1p-11f, acc[mt][nt][3], zhi) + e1; top2_ins(b1h,i1h,b2h,i2h,d,nA+1);
        }
        #pragma unroll
        for (int mask = 1; mask <= 2; mask <<= 1) {
            float w1, w2; int j1, j2;
            w1 = __shfl_xor_sync(0xffffffffu, b1l, mask);
            j1 = __shfl_xor_sync(0xffffffffu, i1l, mask);
            w2 = __shfl_xor_sync(0xffffffffu, b2l, mask);
            j2 = __shfl_xor_sync(0xffffffffu, i2l, mask);
            top2_merge(b1l, i1l, b2l, i2l, w1, j1, w2, j2);
            w1 = __shfl_xor_sync(0xffffffffu, b1h, mask);
            j1 = __shfl_xor_sync(0xffffffffu, i1h, mask);
            w2 = __shfl_xor_sync(0xffffffffu, b2h, mask);
            j2 = __shfl_xor_sync(0xffffffffu, i2h, mask);
            top2_merge(b1h, i1h, b2h, i2h, w1, j1, w2, j2);
        }
        if (tq == 0) {
            sval[rl * 4 + wn * 2]           = b1l;  sidx[rl * 4 + wn * 2]           = i1l;
            sval[rl * 4 + wn * 2 + 1]       = b2l;  sidx[rl * 4 + wn * 2 + 1]       = i2l;
            sval[(rl + 8) * 4 + wn * 2]     = b1h;  sidx[(rl + 8) * 4 + wn * 2]     = i1h;
            sval[(rl + 8) * 4 + wn * 2 + 1] = b2h;  sidx[(rl + 8) * 4 + wn * 2 + 1] = i2h;
        }
    }
    __syncthreads();

    {   // 256 threads: one row each; merge the two wn top-2 sets, store top-2.
        float b1 = sval[tid * 4],     b2 = sval[tid * 4 + 1];
        int   i1 = sidx[tid * 4],     i2 = sidx[tid * 4 + 1];
        top2_merge(b1, i1, b2, i2, sval[tid * 4 + 2], sidx[tid * 4 + 2],
                                   sval[tid * 4 + 3], sidx[tid * 4 + 3]);
        size_t o = ((size_t)(m0 + tid) * NCHUNKS + nt_blk) * 2;
        g_pmin2[o]     = b1;  g_pidx2[o]     = i1;
        g_pmin2[o + 1] = b2;  g_pidx2[o + 1] = i2;
    }
}

// ---------------------------------------------------------------------------
// Exact rescore: one warp per row. Global approx min m*; every candidate
// within m* + EPS gets an exact fp32 distance; argmin with index tie-break.
// The true winner always qualifies (EPS >= 2 * worst-case approx error).
// ---------------------------------------------------------------------------
__global__ void vq_rescore(const float* __restrict__ cbk,
                           float* __restrict__ out_codes_f) {
    int row  = blockIdx.x * 8 + (threadIdx.x >> 5);
    int lane = threadIdx.x & 31;
    const float* pm = g_pmin2 + (size_t)row * (NCHUNKS * 2);
    const int*   pi = g_pidx2 + (size_t)row * (NCHUNKS * 2);

    float m = FLT_MAX;
    #pragma unroll
    for (int j = lane; j < NCHUNKS * 2; j += 32) m = fminf(m, pm[j]);
    #pragma unroll
    for (int off = 16; off > 0; off >>= 1)
        m = fminf(m, __shfl_xor_sync(0xffffffffu, m, off));
    const float thr = m + RESCORE_EPS;

    const float zs = g_zsq[row];
    const float4* zr = (const float4*)(g_zT + (size_t)row * CDIM);
    float4 za = zr[lane];
    float4 zb = zr[lane + 32];

    float bestd = FLT_MAX;
    int   besti = 0x7fffffff;
    for (int j = 0; j < NCHUNKS * 2; j++) {
        if (pm[j] > thr) continue;
        int idx = pi[j];
        const float4* br = (const float4*)(cbk + (size_t)idx * CDIM);
        float4 ba = br[lane];
        float4 bb = br[lane + 32];
        float part = za.x * ba.x + za.y * ba.y + za.z * ba.z + za.w * ba.w
                   + zb.x * bb.x + zb.y * bb.y + zb.z * bb.z + zb.w * bb.w;
        #pragma unroll
        for (int off = 16; off > 0; off >>= 1)
            part += __shfl_xor_sync(0xffffffffu, part, off);
        float d = (zs - 2.0f * part) + __ldg(&g_esq[idx]);
        if (d < bestd || (d == bestd && idx < besti)) { bestd = d; besti = idx; }
    }
    if (lane == 0) {
        g_codes[row]     = besti;
        out_codes_f[row] = (float)besti;
    }
}

// ---------------------------------------------------------------------------
// Gather quantized output (straight-through) + loss partials.
// ---------------------------------------------------------------------------
__global__ void vq_gather_kernel(const float* __restrict__ z,
                                 const float* __restrict__ cbk,
                                 float* __restrict__ out_q) {
    __shared__ float sred[256];
    const float4* z4 = (const float4*)z;
    float4* q4 = (float4*)out_q;
    float accum = 0.f;
    #pragma unroll
    for (int j = 0; j < 2; j++) {
        int i = j * 524288 + blockIdx.x * 256 + threadIdx.x;   // f4 index
        int e  = i << 2;
        int hw = e & 1023;
        int c  = (e >> 10) & 255;
        int b  = e >> 18;
        const int* cd = &g_codes[(b << 10) + hw];
        float4 zv = z4[i];
        float4 qv;
        qv.x = __ldg(&cbk[(size_t)cd[0] * CDIM + c]);
        qv.y = __ldg(&cbk[(size_t)cd[1] * CDIM + c]);
        qv.z = __ldg(&cbk[(size_t)cd[2] * CDIM + c]);
        qv.w = __ldg(&cbk[(size_t)cd[3] * CDIM + c]);
        float dx = qv.x - zv.x, dy = qv.y - zv.y;
        float dz = qv.z - zv.z, dw = qv.w - zv.w;
        float4 o;
        o.x = zv.x + dx; o.y = zv.y + dy; o.z = zv.z + dz; o.w = zv.w + dw;
        q4[i] = o;
        accum += dx * dx + dy * dy + dz * dz + dw * dw;
    }
    sred[threadIdx.x] = accum;
    __syncthreads();
    #pragma unroll
    for (int off = 128; off > 0; off >>= 1) {
        if (threadIdx.x < off) sred[threadIdx.x] += sred[threadIdx.x + off];
        __syncthreads();
    }
    if (threadIdx.x == 0) g_partial[blockIdx.x] = sred[0];
}

__global__ void vq_finalize_kernel(float* __restrict__ out_loss) {
    __shared__ float s[256];
    float a = 0.f;
    for (int i = threadIdx.x; i < 2048; i += 256) a += g_partial[i];
    s[threadIdx.x] = a;
    __syncthreads();
    #pragma unroll
    for (int off = 128; off > 0; off >>= 1) {
        if (threadIdx.x < off) s[threadIdx.x] += s[threadIdx.x + off];
        __syncthreads();
    }
    if (threadIdx.x == 0)
        out_loss[0] = s[0] * (1.25f / (float)NELEM);
}

// ---------------------------------------------------------------------------
extern "C" void kernel_launch(void* const* d_in, const int* in_sizes, int n_in,
                              void* d_out, int out_size) {
    const float* z   = (const float*)d_in[0];   // (16,256,32,32) f32
    const float* cbk = (const float*)d_in[1];   // (8192,256) f32

    float* out       = (float*)d_out;
    float* out_codes = out;                     // 16384
    float* out_q     = out + NROWS;             // 4194304
    float* out_loss  = out + NROWS + NELEM;     // 1

    cudaFuncSetAttribute(vq_gemm, cudaFuncAttributeMaxDynamicSharedMemorySize,
                         SMEM_NEED);

    vq_esq_kernel<<<KCODES / 8, 256>>>(cbk);
    vq_split_cb<<<(KCODES * CDIM) / 256, 256>>>(cbk);
    vq_split_z<<<dim3(HW / 32, CDIM / 32, BATCH), 256>>>(z);
    vq_zsq_kernel<<<NROWS / 8, 256>>>();
    vq_gemm<<<(NROWS / MTILE) * (KCODES / NTILE), 256, SMEM_NEED>>>();
    vq_rescore<<<NROWS / 8, 256>>>(cbk, out_codes);
    vq_gather_kernel<<<2048, 256>>>(z, cbk, out_q);
    vq_finalize_kernel<<<1, 256>>>(out_loss);
}

// round 13
// speedup vs baseline: 1.8729x; 1.8729x over previous
#include <cuda_runtime.h>
#include <cuda_fp16.h>
#include <float.h>
#include <stdint.h>

// ---------------------------------------------------------------------------
// Problem constants
// ---------------------------------------------------------------------------
#define BATCH   16
#define CDIM    256
#define HW      1024
#define NROWS   16384          // BATCH*HW
#define KCODES  8192
#define NELEM   4194304        // BATCH*CDIM*HW

// GEMM config: single-pass fp16 hi*hi (K = 256 halves, 4 chunks of 64).
// B pre-scaled by 2^12; exact fp32 rescore of shortlist fixes approximation.
#define MTILE       256
#define NTILE       128
#define NCHUNKS     64         // 8192 / 128 n-chunks per row
#define NKCH        4
#define STAGES      4
#define STAGE_BYTES 49152      // A 32K (256 rows x 128B) + B 16K (128 x 128B)
#define B_OFF       32768
#define SMEM_NEED   (STAGES * STAGE_BYTES)   // 192 KB

#define RESCORE_EPS 2e-4f      // >= 2 * worst-case fp16-approx distance error

// ---------------------------------------------------------------------------
// Device scratch (no cudaMalloc allowed)
// ---------------------------------------------------------------------------
__device__ __align__(16) __half g_Ahi[NROWS * CDIM];
__device__ __align__(16) __half g_Bhi[KCODES * CDIM];
__device__ __align__(16) float  g_zT [NROWS * CDIM];   // exact fp32, (n,c)
__device__ float g_esq[KCODES];
__device__ float g_zsq[NROWS];
__device__ float g_pmin2[NROWS * NCHUNKS * 2];
__device__ int   g_pidx2[NROWS * NCHUNKS * 2];
__device__ int   g_codes[NROWS];
__device__ float g_partial[2048];

// ---------------------------------------------------------------------------
// Helpers
// ---------------------------------------------------------------------------
__device__ __forceinline__ uint32_t smem_u32(const void* p) {
    uint32_t a;
    asm("{ .reg .u64 t; cvta.to.shared.u64 t, %1; cvt.u32.u64 %0, t; }"
        : "=r"(a) : "l"(p));
    return a;
}

// SW128-style swizzle (relative to tile base; 16B-granular)
#define SWZ(o) ((o) ^ (((o) >> 3) & 0x70))

__device__ __forceinline__ void cp_async16(uint32_t dst, const void* src) {
    asm volatile("cp.async.cg.shared.global [%0], [%1], 16;"
                 :: "r"(dst), "l"(src) : "memory");
}
#define CP_COMMIT() asm volatile("cp.async.commit_group;" ::: "memory")

__device__ __forceinline__ void mma_f16(float* c, const uint32_t* a,
                                        const uint32_t* b) {
    asm volatile(
        "mma.sync.aligned.m16n8k16.row.col.f32.f16.f16.f32 "
        "{%0,%1,%2,%3}, {%4,%5,%6,%7}, {%8,%9}, {%0,%1,%2,%3};"
        : "+f"(c[0]), "+f"(c[1]), "+f"(c[2]), "+f"(c[3])
        : "r"(a[0]), "r"(a[1]), "r"(a[2]), "r"(a[3]), "r"(b[0]), "r"(b[1]));
}

// Packed (distance, index) key: distances are ~256 > 0, so the fp32 bit
// pattern is order-preserving; ties fall through to the smaller index —
// exactly the reference first-index tie-break.
__device__ __forceinline__ uint64_t pack_di(float d, int n) {
    return ((uint64_t)__float_as_uint(d) << 32) | (uint32_t)n;
}
// Branchless top-2 insert on packed keys (3 u64 min/max, no branches).
__device__ __forceinline__ void top2u(uint64_t& b1, uint64_t& b2, uint64_t k) {
    uint64_t hi = k > b1 ? k : b1;
    b1 = k < b1 ? k : b1;
    b2 = hi < b2 ? hi : b2;
}

// ---------------------------------------------------------------------------
// Split codebook -> fp16 hi (pre-scaled by 2^12, exact power of two)
// fused with e_sq[k] = sum_c codebook[k][c]^2 (fp32, warp-tree reduce)
// ---------------------------------------------------------------------------
__global__ void vq_split_cb(const float* __restrict__ cbk) {
    int k    = blockIdx.x * 8 + (threadIdx.x >> 5);
    int lane = threadIdx.x & 31;
    const float4* row = (const float4*)(cbk + (size_t)k * CDIM);
    __half2* dst = (__half2*)(g_Bhi + (size_t)k * CDIM);
    float s = 0.f;
    #pragma unroll
    for (int i = lane; i < CDIM / 4; i += 32) {
        float4 v = row[i];
        s += v.x * v.x + v.y * v.y + v.z * v.z + v.w * v.w;
        dst[i * 2]     = __floats2half2_rn(v.x * 4096.0f, v.y * 4096.0f);
        dst[i * 2 + 1] = __floats2half2_rn(v.z * 4096.0f, v.w * 4096.0f);
    }
    #pragma unroll
    for (int off = 16; off > 0; off >>= 1)
        s += __shfl_down_sync(0xffffffffu, s, off);
    if (lane == 0) g_esq[k] = s;
}

// ---------------------------------------------------------------------------
// Split z -> fp16 hi (for GEMM) + exact fp32 transposed copy (for rescore)
// ---------------------------------------------------------------------------
__global__ void vq_split_z(const float* __restrict__ z) {
    __shared__ float t[32][33];
    int b   = blockIdx.z;
    int c0  = blockIdx.y * 32;
    int hw0 = blockIdx.x * 32;
    int tx  = threadIdx.x & 31;
    int ty  = threadIdx.x >> 5;        // 0..7
    const float* src = z + ((size_t)b * CDIM + c0) * HW + hw0;
    #pragma unroll
    for (int j = 0; j < 4; j++) {
        int c = ty + j * 8;
        t[c][tx] = src[(size_t)c * HW + tx];
    }
    __syncthreads();
    #pragma unroll
    for (int j = 0; j < 4; j++) {
        int hh = ty + j * 8;
        float a  = t[tx][hh];
        size_t o = ((size_t)(b * HW + hw0 + hh)) * CDIM + c0 + tx;
        g_Ahi[o] = __float2half_rn(a);
        g_zT[o]  = a;
    }
}

// ---------------------------------------------------------------------------
// z_sq[n] from the transposed fp32 copy (coalesced; run AFTER vq_split_z)
// ---------------------------------------------------------------------------
__global__ void vq_zsq_kernel() {
    int n    = blockIdx.x * 8 + (threadIdx.x >> 5);
    int lane = threadIdx.x & 31;
    const float4* row = (const float4*)(g_zT + (size_t)n * CDIM);
    float s = 0.f;
    #pragma unroll
    for (int i = lane; i < CDIM / 4; i += 32) {
        float4 v = row[i];
        s += v.x * v.x + v.y * v.y + v.z * v.z + v.w * v.w;
    }
    #pragma unroll
    for (int off = 16; off > 0; off >>= 1)
        s += __shfl_down_sync(0xffffffffu, s, off);
    if (lane == 0) g_zsq[n] = s;
}

// ---------------------------------------------------------------------------
// Stage loader: chunk c (0..3) into pipeline slot s.
// A: 256 rows x 128B (64 halves); B: 128 rows x 128B.
// ---------------------------------------------------------------------------
__device__ __forceinline__ void load_stage(uint32_t sbu, int c, int s,
                                           int m0, int n0, int tid) {
    int kb = c * 64;                        // halves
    uint32_t st = sbu + s * STAGE_BYTES;
    #pragma unroll
    for (int j = 0; j < 8; j++) {           // A: 2048 cp16
        int id = j * 256 + tid;
        int r = id >> 3, q = id & 7;
        cp_async16(st + SWZ(r * 128 + q * 16),
                   g_Ahi + (size_t)(m0 + r) * CDIM + kb + q * 8);
    }
    #pragma unroll
    for (int j = 0; j < 4; j++) {           // B: 1024 cp16
        int id = j * 256 + tid;
        int r = id >> 3, q = id & 7;
        cp_async16(st + B_OFF + SWZ(r * 128 + q * 16),
                   g_Bhi + (size_t)(n0 + r) * CDIM + kb + q * 8);
    }
}

// ---------------------------------------------------------------------------
// Main mma.sync fp16 GEMM + fused approx distance / branchless top-2.
// Grid: 4096 CTAs = 64 m-tiles (256 rows) x 64 n-chunks (128 codes).
// 8 warps, warp tile 64x64. All 4 K-chunks prefetched up front.
// ---------------------------------------------------------------------------
__global__ __launch_bounds__(256, 1) void vq_gemm() {
    extern __shared__ char smem_raw[];
    const uint32_t sbu = smem_u32(smem_raw);
    const int tid  = threadIdx.x;
    const int lane = tid & 31;
    const int wid  = tid >> 5;
    const int wm   = wid & 3;          // 4 m-blocks of 64
    const int wn   = wid >> 2;         // 2 n-blocks of 64
    const int gq   = lane >> 2;        // 0..7
    const int tq   = lane & 3;         // 0..3

    const int nt_blk = blockIdx.x & 63;
    const int mt_blk = blockIdx.x >> 6;
    const int m0 = mt_blk * MTILE;
    const int n0 = nt_blk * NTILE;

    const uint32_t rxor = (uint32_t)gq << 4;
    uint32_t coff[8];
    #pragma unroll
    for (int ks = 0; ks < 4; ks++) {
        uint32_t base = ks * 32 + tq * 4;
        coff[2 * ks]     = base ^ rxor;
        coff[2 * ks + 1] = (base + 16) ^ rxor;
    }
    uint32_t rA[4], rB[8];
    #pragma unroll
    for (int mt = 0; mt < 4; mt++) rA[mt] = (uint32_t)(wm * 64 + mt * 16 + gq) * 128;
    #pragma unroll
    for (int nt = 0; nt < 8; nt++) rB[nt] = (uint32_t)(wn * 64 + nt * 8 + gq) * 128;

    float acc[4][8][4];
    #pragma unroll
    for (int mt = 0; mt < 4; mt++)
        #pragma unroll
        for (int nt = 0; nt < 8; nt++)
            #pragma unroll
            for (int r = 0; r < 4; r++) acc[mt][nt][r] = 0.f;

    // Prefetch ALL 4 chunks (whole K) into the 4 stages
    #pragma unroll
    for (int s = 0; s < 4; s++) { load_stage(sbu, s, s, m0, n0, tid); CP_COMMIT(); }

    for (int c = 0; c < NKCH; c++) {
        if (c == 0)      asm volatile("cp.async.wait_group 3;" ::: "memory");
        else if (c == 1) asm volatile("cp.async.wait_group 2;" ::: "memory");
        else if (c == 2) asm volatile("cp.async.wait_group 1;" ::: "memory");
        else             asm volatile("cp.async.wait_group 0;" ::: "memory");
        __syncthreads();

        const char* stA = smem_raw + c * STAGE_BYTES;
        const char* stB = stA + B_OFF;
        #pragma unroll
        for (int ks = 0; ks < 4; ks++) {
            uint32_t a[4][4], b[8][2];
            #pragma unroll
            for (int mt = 0; mt < 4; mt++) {
                a[mt][0] = *(const uint32_t*)(stA + rA[mt] + coff[2 * ks]);
                a[mt][1] = *(const uint32_t*)(stA + rA[mt] + 1024 + coff[2 * ks]);
                a[mt][2] = *(const uint32_t*)(stA + rA[mt] + coff[2 * ks + 1]);
                a[mt][3] = *(const uint32_t*)(stA + rA[mt] + 1024 + coff[2 * ks + 1]);
            }
            #pragma unroll
            for (int nt = 0; nt < 8; nt++) {
                b[nt][0] = *(const uint32_t*)(stB + rB[nt] + coff[2 * ks]);
                b[nt][1] = *(const uint32_t*)(stB + rB[nt] + coff[2 * ks + 1]);
            }
            #pragma unroll
            for (int mt = 0; mt < 4; mt++)
                #pragma unroll
                for (int nt = 0; nt < 8; nt++)
                    mma_f16(acc[mt][nt], a[mt], b[nt]);
        }
    }

    __syncthreads();   // stages done; smem reused for reduction

    // Epilogue: approx distances (unscale folded: -2 * 2^-12), packed top-2.
    uint64_t* skey = (uint64_t*)smem_raw;      // [256 rows][2 wn][2] = 8 KB

    #pragma unroll
    for (int mt = 0; mt < 4; mt++) {
        const int rl  = wm * 64 + mt * 16 + gq;
        const float zlo = g_zsq[m0 + rl];
        const float zhi = g_zsq[m0 + rl + 8];
        uint64_t k1l = ~0ull, k2l = ~0ull, k1h = ~0ull, k2h = ~0ull;
        #pragma unroll
        for (int nt = 0; nt < 8; nt++) {
            const int nA = n0 + wn * 64 + nt * 8 + 2 * tq;
            const float e0 = __ldg(&g_esq[nA]);
            const float e1 = __ldg(&g_esq[nA + 1]);
            float d;
            d = fmaf(-0x1p-11f, acc[mt][nt][0], zlo) + e0; top2u(k1l, k2l, pack_di(d, nA));
            d = fmaf(-0x1p-11f, acc[mt][nt][1], zlo) + e1; top2u(k1l, k2l, pack_di(d, nA + 1));
            d = fmaf(-0x1p-11f, acc[mt][nt][2], zhi) + e0; top2u(k1h, k2h, pack_di(d, nA));
            d = fmaf(-0x1p-11f, acc[mt][nt][3], zhi) + e1; top2u(k1h, k2h, pack_di(d, nA + 1));
        }
        #pragma unroll
        for (int mask = 1; mask <= 2; mask <<= 1) {
            uint64_t o1, o2;
            o1 = __shfl_xor_sync(0xffffffffu, k1l, mask);
            o2 = __shfl_xor_sync(0xffffffffu, k2l, mask);
            top2u(k1l, k2l, o1); top2u(k1l, k2l, o2);
            o1 = __shfl_xor_sync(0xffffffffu, k1h, mask);
            o2 = __shfl_xor_sync(0xffffffffu, k2h, mask);
            top2u(k1h, k2h, o1); top2u(k1h, k2h, o2);
        }
        if (tq == 0) {
            skey[rl * 4 + wn * 2]           = k1l;
            skey[rl * 4 + wn * 2 + 1]       = k2l;
            skey[(rl + 8) * 4 + wn * 2]     = k1h;
            skey[(rl + 8) * 4 + wn * 2 + 1] = k2h;
        }
    }
    __syncthreads();

    {   // 256 threads: one row each; merge the two wn top-2 sets, store top-2.
        uint64_t b1 = ~0ull, b2 = ~0ull;
        top2u(b1, b2, skey[tid * 4]);
        top2u(b1, b2, skey[tid * 4 + 1]);
        top2u(b1, b2, skey[tid * 4 + 2]);
        top2u(b1, b2, skey[tid * 4 + 3]);
        size_t o = ((size_t)(m0 + tid) * NCHUNKS + nt_blk) * 2;
        g_pmin2[o]     = __uint_as_float((uint32_t)(b1 >> 32));
        g_pidx2[o]     = (int)(uint32_t)b1;
        g_pmin2[o + 1] = __uint_as_float((uint32_t)(b2 >> 32));
        g_pidx2[o + 1] = (int)(uint32_t)b2;
    }
}

// ---------------------------------------------------------------------------
// Exact rescore, lane-parallel: one warp per row. Each lane holds 4 of the
// 128 shortlist entries; ballot selects candidates within m* + EPS; the whole
// warp computes each exact fp32 distance. The true winner always qualifies
// (EPS >= 2 * worst-case approx error).
// ---------------------------------------------------------------------------
__global__ void vq_rescore(const float* __restrict__ cbk,
                           float* __restrict__ out_codes_f) {
    int row  = blockIdx.x * 8 + (threadIdx.x >> 5);
    int lane = threadIdx.x & 31;
    const float* pm = g_pmin2 + (size_t)row * (NCHUNKS * 2);
    const int*   pi = g_pidx2 + (size_t)row * (NCHUNKS * 2);

    float v[4]; int idv[4];
    float m = FLT_MAX;
    #pragma unroll
    for (int g = 0; g < 4; g++) {
        v[g]   = pm[lane + 32 * g];
        idv[g] = pi[lane + 32 * g];
        m = fminf(m, v[g]);
    }
    #pragma unroll
    for (int off = 16; off > 0; off >>= 1)
        m = fminf(m, __shfl_xor_sync(0xffffffffu, m, off));
    const float thr = m + RESCORE_EPS;

    const float zs = g_zsq[row];
    const float4* zr = (const float4*)(g_zT + (size_t)row * CDIM);
    float4 za = zr[lane];
    float4 zb = zr[lane + 32];

    float bestd = FLT_MAX;
    int   besti = 0x7fffffff;
    #pragma unroll
    for (int g = 0; g < 4; g++) {
        unsigned msk = __ballot_sync(0xffffffffu, v[g] <= thr);
        while (msk) {
            int bit = __ffs(msk) - 1;
            msk &= msk - 1;
            int idx = __shfl_sync(0xffffffffu, idv[g], bit);
            const float4* br = (const float4*)(cbk + (size_t)idx * CDIM);
            float4 ba = br[lane];
            float4 bb = br[lane + 32];
            float part = za.x * ba.x + za.y * ba.y + za.z * ba.z + za.w * ba.w
                       + zb.x * bb.x + zb.y * bb.y + zb.z * bb.z + zb.w * bb.w;
            #pragma unroll
            for (int off = 16; off > 0; off >>= 1)
                part += __shfl_xor_sync(0xffffffffu, part, off);
            float d = (zs - 2.0f * part) + __ldg(&g_esq[idx]);
            if (d < bestd || (d == bestd && idx < besti)) { bestd = d; besti = idx; }
        }
    }
    if (lane == 0) {
        g_codes[row]     = besti;
        out_codes_f[row] = (float)besti;
    }
}

// ---------------------------------------------------------------------------
// Gather quantized output (straight-through) + loss partials.
// ---------------------------------------------------------------------------
__global__ void vq_gather_kernel(const float* __restrict__ z,
                                 const float* __restrict__ cbk,
                                 float* __restrict__ out_q) {
    __shared__ float sred[256];
    const float4* z4 = (const float4*)z;
    float4* q4 = (float4*)out_q;
    float accum = 0.f;
    #pragma unroll
    for (int j = 0; j < 2; j++) {
        int i = j * 524288 + blockIdx.x * 256 + threadIdx.x;   // f4 index
        int e  = i << 2;
        int hw = e & 1023;
        int c  = (e >> 10) & 255;
        int b  = e >> 18;
        const int* cd = &g_codes[(b << 10) + hw];
        float4 zv = z4[i];
        float4 qv;
        qv.x = __ldg(&cbk[(size_t)cd[0] * CDIM + c]);
        qv.y = __ldg(&cbk[(size_t)cd[1] * CDIM + c]);
        qv.z = __ldg(&cbk[(size_t)cd[2] * CDIM + c]);
        qv.w = __ldg(&cbk[(size_t)cd[3] * CDIM + c]);
        float dx = qv.x - zv.x, dy = qv.y - zv.y;
        float dz = qv.z - zv.z, dw = qv.w - zv.w;
        float4 o;
        o.x = zv.x + dx; o.y = zv.y + dy; o.z = zv.z + dz; o.w = zv.w + dw;
        q4[i] = o;
        accum += dx * dx + dy * dy + dz * dz + dw * dw;
    }
    sred[threadIdx.x] = accum;
    __syncthreads();
    #pragma unroll
    for (int off = 128; off > 0; off >>= 1) {
        if (threadIdx.x < off) sred[threadIdx.x] += sred[threadIdx.x + off];
        __syncthreads();
    }
    if (threadIdx.x == 0) g_partial[blockIdx.x] = sred[0];
}

__global__ void vq_finalize_kernel(float* __restrict__ out_loss) {
    __shared__ float s[256];
    float a = 0.f;
    for (int i = threadIdx.x; i < 2048; i += 256) a += g_partial[i];
    s[threadIdx.x] = a;
    __syncthreads();
    #pragma unroll
    for (int off = 128; off > 0; off >>= 1) {
        if (threadIdx.x < off) s[threadIdx.x] += s[threadIdx.x + off];
        __syncthreads();
    }
    if (threadIdx.x == 0)
        out_loss[0] = s[0] * (1.25f / (float)NELEM);
}

// ---------------------------------------------------------------------------
extern "C" void kernel_launch(void* const* d_in, const int* in_sizes, int n_in,
                              void* d_out, int out_size) {
    const float* z   = (const float*)d_in[0];   // (16,256,32,32) f32
    const float* cbk = (const float*)d_in[1];   // (8192,256) f32

    float* out       = (float*)d_out;
    float* out_codes = out;                     // 16384
    float* out_q     = out + NROWS;             // 4194304
    float* out_loss  = out + NROWS + NELEM;     // 1

    cudaFuncSetAttribute(vq_gemm, cudaFuncAttributeMaxDynamicSharedMemorySize,
                         SMEM_NEED);

    vq_split_cb<<<KCODES / 8, 256>>>(cbk);
    vq_split_z<<<dim3(HW / 32, CDIM / 32, BATCH), 256>>>(z);
    vq_zsq_kernel<<<NROWS / 8, 256>>>();
    vq_gemm<<<(NROWS / MTILE) * (KCODES / NTILE), 256, SMEM_NEED>>>();
    vq_rescore<<<NROWS / 8, 256>>>(cbk, out_codes);
    vq_gather_kernel<<<2048, 256>>>(z, cbk, out_q);
    vq_finalize_kernel<<<1, 256>>>(out_loss);
}